// round 11
// baseline (speedup 1.0000x reference)
#include <cuda_runtime.h>
#include <cuda_fp16.h>
#include <cstdint>

// ---------------- problem constants ----------------
#define B_TOK 65536
#define I_DIM 512
#define H_DIM 128
#define T_NUM 2
#define ETOT  6
#define NE    8                 // packed experts: t0e0,t0e1,t1e0,t1e1,c0..c3
#define N_DIM (NE * H_DIM)      // 1024
#define K_DIM 512
#define NQ    14                // 12 logit weights + 2 Wt-dot weights

// ---------------- scratch (device globals; no allocs allowed) ----------------
__device__ __align__(256) __half g_xh[(size_t)B_TOK * K_DIM];     // fp16 x (64 MB)
__device__ __align__(256) __half g_Wh[N_DIM * K_DIM];             // [n][k] fp16 (1 MB)
__device__ __align__(256) float  g_bpack[N_DIM];
__device__ __align__(256) float  g_Wg2[NE * H_DIM * NQ];          // [e][h][q]
__device__ __align__(256) float  g_part[(size_t)NE * 2 * B_TOK * 16]; // [e][wn][b][16]

// ---------------- helpers ----------------
__device__ __forceinline__ void mma16(float* c, const uint32_t* a, const uint32_t* b) {
    asm volatile(
        "mma.sync.aligned.m16n8k16.row.col.f32.f16.f16.f32 "
        "{%0,%1,%2,%3}, {%4,%5,%6,%7}, {%8,%9}, {%0,%1,%2,%3};"
        : "+f"(c[0]), "+f"(c[1]), "+f"(c[2]), "+f"(c[3])
        : "r"(a[0]), "r"(a[1]), "r"(a[2]), "r"(a[3]), "r"(b[0]), "r"(b[1]));
}
#define LDSM_X4(r0, r1, r2, r3, addr) \
    asm volatile("ldmatrix.sync.aligned.m8n8.x4.shared.b16 {%0,%1,%2,%3}, [%4];" \
                 : "=r"(r0), "=r"(r1), "=r"(r2), "=r"(r3) : "r"(addr))
#define CP_ASYNC16(dst, src) \
    asm volatile("cp.async.cg.shared.global [%0], [%1], 16;\n" :: "r"(dst), "l"(src))
#define CP_COMMIT() asm volatile("cp.async.commit_group;\n")
#define CP_WAIT2()  asm volatile("cp.async.wait_group 2;\n")
#define CP_WAIT0()  asm volatile("cp.async.wait_group 0;\n")

__device__ __forceinline__ uint32_t smem_u32(const void* p) {
    uint32_t a;
    asm("{ .reg .u64 t; cvta.to.shared.u64 t, %1; cvt.u32.u64 %0, t; }"
        : "=r"(a) : "l"(p));
    return a;
}

// ---------------- kernel 1: convert x, pack W, build gate table ----------------
__global__ void prep_kernel(const float* __restrict__ x,
                            const float* __restrict__ Wc, const float* __restrict__ bc,
                            const float* __restrict__ Ws, const float* __restrict__ bs,
                            const float* __restrict__ Wg, const float* __restrict__ Wt) {
    const int idx = blockIdx.x * blockDim.x + threadIdx.x;   // 0 .. 8388607

    {
        float4 v = reinterpret_cast<const float4*>(x)[idx];
        __half2 h0 = __floats2half2_rn(v.x, v.y);
        __half2 h1 = __floats2half2_rn(v.z, v.w);
        uint2 pk = make_uint2(*reinterpret_cast<uint32_t*>(&h0),
                              *reinterpret_cast<uint32_t*>(&h1));
        reinterpret_cast<uint2*>(g_xh)[idx] = pk;
    }
    if (idx < N_DIM * K_DIM) {
        int n = idx / K_DIM, k = idx % K_DIM;
        int e = n / H_DIM,   h = n % H_DIM;
        float v = (e < 4) ? Ws[((size_t)e * I_DIM + k) * H_DIM + h]
                          : Wc[((size_t)(e - 4) * I_DIM + k) * H_DIM + h];
        g_Wh[idx] = __float2half(v);
    }
    if (idx < N_DIM) {
        int e = idx / H_DIM, h = idx % H_DIM;
        g_bpack[idx] = (e < 4) ? bs[e * H_DIM + h] : bc[(e - 4) * H_DIM + h];
    }
    if (idx < NE * H_DIM * NQ) {
        int e = idx / (H_DIM * NQ);
        int rem = idx % (H_DIM * NQ);
        int h = rem / NQ, q = rem % NQ;
        float v;
        if (q < 12) {
            int t = q / ETOT, j = q % ETOT;
            bool active; int f = 0;
            if (e < 4) { active = ((e >> 1) == t); f = e & 1; }
            else       { active = true;            f = e - 2; }
            v = active ? Wg[((size_t)t * (ETOT * H_DIM) + f * H_DIM + h) * ETOT + j] : 0.f;
        } else {
            v = Wt[(q - 12) * H_DIM + h];
        }
        g_Wg2[idx] = v;
    }
}

// ---------------- kernel 2: fp16 GEMM (ldmatrix + m16n8k16) + gate epilogue -----
#define BM 256
#define BN 128
#define BKH 64                 // K halves per chunk
#define NCHUNK (K_DIM / BKH)   // 8
#define NSTAGE 4
#define A_PITCH 72             // halves; 144 B rows -> LDSM conflict-free
#define A_SZ (BM * A_PITCH)    // 18432 halves
#define B_SZ (BN * A_PITCH)    // 9216 halves
#define STG_H (A_SZ + B_SZ)
#define SMEM_BYTES (NSTAGE * STG_H * 2)   // 221184 B

__global__ __launch_bounds__(256) void gemm_kernel() {
    extern __shared__ __half smem[];

    const int tid  = threadIdx.x;
    const int wid  = tid >> 5, lane = tid & 31;
    const int g    = lane >> 2, tg = lane & 3;
    const int wm   = wid >> 1, wn = wid & 1;        // 4x2 warp grid, 64x64 per warp
    const int e    = blockIdx.x;
    const int m0   = blockIdx.y * BM;
    const int n0   = e * BN;

    // ldmatrix lane-address offsets (in bytes, within a stage)
    // A x4: lanes 0-15 -> rows r0+l (k 0-7), lanes 16-31 -> rows r0+l-16 (k 8-15)
    const uint32_t offA =
        (uint32_t)(((wm * 64 + (lane & 15)) * A_PITCH + ((lane >> 4) << 3)) * 2);
    // B x4: lanes 0-7: n c0+l, k0-7 | 8-15: n c0+l-8, k8-15 | 16-23: n c0+8+l-16, k0-7 | 24-31: n c0+8+l-24, k8-15
    const uint32_t offB =
        (uint32_t)((A_SZ + (wn * 64 + (lane & 7) + ((lane >> 4) << 3)) * A_PITCH +
                    (((lane >> 3) & 1) << 3)) * 2);

    float acc[4][8][4];
    #pragma unroll
    for (int i = 0; i < 4; i++)
        #pragma unroll
        for (int j = 0; j < 8; j++)
            #pragma unroll
            for (int c = 0; c < 4; c++) acc[i][j][c] = 0.f;

    auto load_stage = [&](int kt, int buf) {
        const int kb = kt * BKH;
        __half* As = smem + buf * STG_H;
        __half* Bs = As + A_SZ;
        const uint32_t sA = smem_u32(As), sB = smem_u32(Bs);
        #pragma unroll
        for (int i = 0; i < 8; i++) {                // A: 256 rows x 8 chunks(16B)
            int f   = tid + i * 256;
            int row = f >> 3, kc = f & 7;
            const __half* src = g_xh + (size_t)(m0 + row) * K_DIM + kb + kc * 8;
            CP_ASYNC16(sA + (uint32_t)(row * A_PITCH + kc * 8) * 2, src);
        }
        #pragma unroll
        for (int i = 0; i < 4; i++) {                // B: 128 rows x 8 chunks(16B)
            int f   = tid + i * 256;
            int row = f >> 3, kc = f & 7;
            const __half* src = g_Wh + (size_t)(n0 + row) * K_DIM + kb + kc * 8;
            CP_ASYNC16(sB + (uint32_t)(row * A_PITCH + kc * 8) * 2, src);
        }
        CP_COMMIT();
    };

    auto compute = [&](int buf) {
        const uint32_t stBase = smem_u32(smem + buf * STG_H);
        #pragma unroll
        for (int ks = 0; ks < 4; ks++) {             // 4 x k16 per chunk
            const uint32_t kOff = (uint32_t)(ks * 16 * 2);   // 16 halves in bytes
            uint32_t af[4][4];
            #pragma unroll
            for (int mt = 0; mt < 4; mt++) {
                uint32_t a = stBase + offA + (uint32_t)(mt * 16 * A_PITCH * 2) + kOff;
                LDSM_X4(af[mt][0], af[mt][1], af[mt][2], af[mt][3], a);
            }
            uint32_t bb[8][2];
            #pragma unroll
            for (int nt2 = 0; nt2 < 4; nt2++) {
                uint32_t a = stBase + offB + (uint32_t)(nt2 * 16 * A_PITCH * 2) + kOff;
                LDSM_X4(bb[nt2 * 2][0], bb[nt2 * 2][1],
                        bb[nt2 * 2 + 1][0], bb[nt2 * 2 + 1][1], a);
            }
            #pragma unroll
            for (int mt = 0; mt < 4; mt++)
                #pragma unroll
                for (int nt = 0; nt < 8; nt++)
                    mma16(acc[mt][nt], af[mt], bb[nt]);
        }
    };

    load_stage(0, 0);
    load_stage(1, 1);
    load_stage(2, 2);
    #pragma unroll 1
    for (int kt = 0; kt < NCHUNK; kt++) {
        if (kt + 3 < NCHUNK) CP_WAIT2(); else CP_WAIT0();
        __syncthreads();
        if (kt + 3 < NCHUNK) load_stage(kt + 3, (kt + 3) % NSTAGE);
        compute(kt % NSTAGE);
    }

    // ---------------- epilogue: gate partials (reuse stage smem) ----------------
    __syncthreads();
    float* sWg = reinterpret_cast<float*>(smem);     // 128*NQ floats
    for (int i = tid; i < H_DIM * NQ; i += 256)
        sWg[i] = g_Wg2[(size_t)e * H_DIM * NQ + i];
    __syncthreads();

    float bias[8][2];
    #pragma unroll
    for (int nt = 0; nt < 8; nt++) {
        int col = n0 + wn * 64 + nt * 8 + 2 * tg;
        bias[nt][0] = g_bpack[col];
        bias[nt][1] = g_bpack[col + 1];
    }

    #pragma unroll
    for (int half = 0; half < 2; half++) {
        float part[4][NQ];
        #pragma unroll
        for (int r = 0; r < 4; r++)
            #pragma unroll
            for (int q = 0; q < NQ; q++) part[r][q] = 0.f;

        #pragma unroll
        for (int nt = 0; nt < 8; nt++)
            #pragma unroll
            for (int h2 = 0; h2 < 2; h2++) {
                int hh = wn * 64 + nt * 8 + 2 * tg + h2;
                float w[NQ];
                #pragma unroll
                for (int q = 0; q < NQ; q++) w[q] = sWg[hh * NQ + q];
                #pragma unroll
                for (int mt2 = 0; mt2 < 2; mt2++)
                    #pragma unroll
                    for (int rr = 0; rr < 2; rr++) {
                        float v = acc[half * 2 + mt2][nt][rr * 2 + h2] + bias[nt][h2];
                        #pragma unroll
                        for (int q = 0; q < NQ; q++) part[mt2 * 2 + rr][q] += v * w[q];
                    }
            }

        #pragma unroll
        for (int r = 0; r < 4; r++) {
            #pragma unroll
            for (int q = 0; q < NQ; q++) {
                part[r][q] += __shfl_xor_sync(0xffffffffu, part[r][q], 1);
                part[r][q] += __shfl_xor_sync(0xffffffffu, part[r][q], 2);
            }
            if (tg == 0) {
                int mt = half * 2 + (r >> 1);
                int row = m0 + wm * 64 + mt * 16 + g + (r & 1) * 8;
                float* dst = g_part + (((size_t)(e * 2 + wn) * B_TOK + row) << 4);
                reinterpret_cast<float4*>(dst)[0] =
                    make_float4(part[r][0], part[r][1], part[r][2],  part[r][3]);
                reinterpret_cast<float4*>(dst)[1] =
                    make_float4(part[r][4], part[r][5], part[r][6],  part[r][7]);
                reinterpret_cast<float4*>(dst)[2] =
                    make_float4(part[r][8], part[r][9], part[r][10], part[r][11]);
                reinterpret_cast<float4*>(dst)[3] =
                    make_float4(part[r][12], part[r][13], 0.f, 0.f);
            }
        }
    }
}

// ---------------- kernel 3: combine partials, softmax, output -------------------
__global__ __launch_bounds__(256) void gate_kernel(const float* __restrict__ bg,
                                                   const float* __restrict__ bt,
                                                   float* __restrict__ out) {
    const int b = blockIdx.x * 256 + threadIdx.x;

    float lg[12];
    #pragma unroll
    for (int q = 0; q < 12; q++) lg[q] = 0.f;
    float dots[NE][2];
    #pragma unroll
    for (int e = 0; e < NE; e++) { dots[e][0] = 0.f; dots[e][1] = 0.f; }

    #pragma unroll
    for (int s = 0; s < 16; s++) {
        const float4* p =
            reinterpret_cast<const float4*>(g_part + (((size_t)s * B_TOK + b) << 4));
        float4 v0 = p[0], v1 = p[1], v2 = p[2], v3 = p[3];
        lg[0] += v0.x; lg[1] += v0.y; lg[2]  += v0.z; lg[3]  += v0.w;
        lg[4] += v1.x; lg[5] += v1.y; lg[6]  += v1.z; lg[7]  += v1.w;
        lg[8] += v2.x; lg[9] += v2.y; lg[10] += v2.z; lg[11] += v2.w;
        int e = s >> 1;
        dots[e][0] += v3.x; dots[e][1] += v3.y;
    }

    #pragma unroll
    for (int t = 0; t < T_NUM; t++) {
        float l[ETOT];
        #pragma unroll
        for (int j = 0; j < ETOT; j++) l[j] = lg[t * ETOT + j] + bg[t * ETOT + j];
        float m = l[0];
        #pragma unroll
        for (int j = 1; j < ETOT; j++) m = fmaxf(m, l[j]);
        float ex[ETOT], ssum = 0.f;
        #pragma unroll
        for (int j = 0; j < ETOT; j++) { ex[j] = expf(l[j] - m); ssum += ex[j]; }
        float inv = 1.f / ssum;
        float o = 0.f;
        #pragma unroll
        for (int eo = 0; eo < ETOT; eo++) {
            int e2 = (eo < 2) ? (2 * t + eo) : (eo + 2);
            o += ex[eo] * inv * dots[e2][t];
        }
        out[t * B_TOK + b] = o + bt[t];
    }
}

// ---------------- launch ----------------
extern "C" void kernel_launch(void* const* d_in, const int* in_sizes, int n_in,
                              void* d_out, int out_size) {
    const float* x  = (const float*)d_in[0];
    const float* Wc = (const float*)d_in[1];
    const float* bc = (const float*)d_in[2];
    const float* Ws = (const float*)d_in[3];
    const float* bs = (const float*)d_in[4];
    const float* Wg = (const float*)d_in[5];
    const float* bg = (const float*)d_in[6];
    const float* Wt = (const float*)d_in[7];
    const float* bt = (const float*)d_in[8];
    float* out = (float*)d_out;

    prep_kernel<<<(B_TOK * K_DIM / 4) / 256, 256>>>(x, Wc, bc, Ws, bs, Wg, Wt);

    cudaFuncSetAttribute(gemm_kernel, cudaFuncAttributeMaxDynamicSharedMemorySize,
                         SMEM_BYTES);
    gemm_kernel<<<dim3(NE, B_TOK / BM), 256, SMEM_BYTES>>>();

    gate_kernel<<<B_TOK / 256, 256>>>(bg, bt, out);
}

// round 13
// speedup vs baseline: 1.6045x; 1.6045x over previous
#include <cuda_runtime.h>
#include <cuda_fp16.h>
#include <cstdint>

// ---------------- problem constants ----------------
#define B_TOK 65536
#define I_DIM 512
#define H_DIM 128
#define T_NUM 2
#define ETOT  6
#define NE    8                 // packed experts: t0e0,t0e1,t1e0,t1e1,c0..c3
#define N_DIM (NE * H_DIM)      // 1024
#define K_DIM 512
#define NQ    14                // 12 logit weights + 2 Wt-dot weights

// ---------------- scratch (device globals; no allocs allowed) ----------------
__device__ __align__(256) __half g_xh[(size_t)B_TOK * K_DIM];     // fp16 x (64 MB)
__device__ __align__(256) __half g_Wh[N_DIM * K_DIM];             // [n][k] fp16 (1 MB)
__device__ __align__(256) float  g_bpack[N_DIM];
__device__ __align__(256) float  g_Wg2[NE * H_DIM * NQ];          // [e][h][q]
__device__ __align__(256) float  g_part[(size_t)NE * 2 * B_TOK * 16]; // [e][wn][b][16]

// ---------------- helpers ----------------
__device__ __forceinline__ void mma16(float* c, const uint32_t* a, const uint32_t* b) {
    asm volatile(
        "mma.sync.aligned.m16n8k16.row.col.f32.f16.f16.f32 "
        "{%0,%1,%2,%3}, {%4,%5,%6,%7}, {%8,%9}, {%0,%1,%2,%3};"
        : "+f"(c[0]), "+f"(c[1]), "+f"(c[2]), "+f"(c[3])
        : "r"(a[0]), "r"(a[1]), "r"(a[2]), "r"(a[3]), "r"(b[0]), "r"(b[1]));
}
#define CP_ASYNC16(dst, src) \
    asm volatile("cp.async.cg.shared.global [%0], [%1], 16;\n" :: "r"(dst), "l"(src))
#define CP_COMMIT() asm volatile("cp.async.commit_group;\n")
#define CP_WAIT2()  asm volatile("cp.async.wait_group 2;\n")
#define CP_WAIT1()  asm volatile("cp.async.wait_group 1;\n")
#define CP_WAIT0()  asm volatile("cp.async.wait_group 0;\n")

__device__ __forceinline__ uint32_t smem_u32(const void* p) {
    uint32_t a;
    asm("{ .reg .u64 t; cvta.to.shared.u64 t, %1; cvt.u32.u64 %0, t; }"
        : "=r"(a) : "l"(p));
    return a;
}

// ---------------- kernel 1: convert x, pack W, build gate table ----------------
__global__ void prep_kernel(const float* __restrict__ x,
                            const float* __restrict__ Wc, const float* __restrict__ bc,
                            const float* __restrict__ Ws, const float* __restrict__ bs,
                            const float* __restrict__ Wg, const float* __restrict__ Wt) {
    const int idx = blockIdx.x * blockDim.x + threadIdx.x;   // 0 .. 8388607

    {
        float4 v = reinterpret_cast<const float4*>(x)[idx];
        __half2 h0 = __floats2half2_rn(v.x, v.y);
        __half2 h1 = __floats2half2_rn(v.z, v.w);
        uint2 pk = make_uint2(*reinterpret_cast<uint32_t*>(&h0),
                              *reinterpret_cast<uint32_t*>(&h1));
        reinterpret_cast<uint2*>(g_xh)[idx] = pk;
    }
    if (idx < N_DIM * K_DIM) {
        int n = idx / K_DIM, k = idx % K_DIM;
        int e = n / H_DIM,   h = n % H_DIM;
        float v = (e < 4) ? Ws[((size_t)e * I_DIM + k) * H_DIM + h]
                          : Wc[((size_t)(e - 4) * I_DIM + k) * H_DIM + h];
        g_Wh[idx] = __float2half(v);
    }
    if (idx < N_DIM) {
        int e = idx / H_DIM, h = idx % H_DIM;
        g_bpack[idx] = (e < 4) ? bs[e * H_DIM + h] : bc[(e - 4) * H_DIM + h];
    }
    if (idx < NE * H_DIM * NQ) {
        int e = idx / (H_DIM * NQ);
        int rem = idx % (H_DIM * NQ);
        int h = rem / NQ, q = rem % NQ;
        float v;
        if (q < 12) {
            int t = q / ETOT, j = q % ETOT;
            bool active; int f = 0;
            if (e < 4) { active = ((e >> 1) == t); f = e & 1; }
            else       { active = true;            f = e - 2; }
            v = active ? Wg[((size_t)t * (ETOT * H_DIM) + f * H_DIM + h) * ETOT + j] : 0.f;
        } else {
            v = Wt[(q - 12) * H_DIM + h];
        }
        g_Wg2[idx] = v;
    }
}

// ---------------- kernel 2: fp16 GEMM (m16n8k16) + gate-partial epilogue --------
// R8 mainloop structure, CTA shrunk to 128x128 / 128 threads -> 2 CTAs per SM.
#define BM 128
#define BN 128
#define BKH 64                 // K halves per chunk (128 B rows)
#define NCHUNK (K_DIM / BKH)   // 8
#define NSTAGE 3
#define A_PITCH 72             // halves; bank = 4g+tg -> conflict-free; 144B % 16 == 0
#define A_SZ (BM * A_PITCH)    // 9216 halves
#define B_SZ (BN * A_PITCH)    // 9216 halves
#define STG_H (A_SZ + B_SZ)
#define SMEM_BYTES (NSTAGE * STG_H * 2)   // 110592 B -> 2 CTAs/SM

__global__ __launch_bounds__(128, 2) void gemm_kernel() {
    extern __shared__ __half smem[];

    const int tid  = threadIdx.x;
    const int wid  = tid >> 5, lane = tid & 31;
    const int g    = lane >> 2, tg = lane & 3;
    const int wm   = wid >> 1, wn = wid & 1;        // 2x2 warp grid, 64x64 per warp
    const int e    = blockIdx.x;
    const int m0   = blockIdx.y * BM;
    const int n0   = e * BN;

    float acc[4][8][4];
    #pragma unroll
    for (int i = 0; i < 4; i++)
        #pragma unroll
        for (int j = 0; j < 8; j++)
            #pragma unroll
            for (int c = 0; c < 4; c++) acc[i][j][c] = 0.f;

    auto load_stage = [&](int kt, int buf) {
        const int kb = kt * BKH;                     // in halves
        __half* As = smem + buf * STG_H;
        __half* Bs = As + A_SZ;
        const uint32_t sA = smem_u32(As), sB = smem_u32(Bs);
        #pragma unroll
        for (int i = 0; i < 8; i++) {                // A: 128 rows x 8 chunks(16B)
            int f   = tid + i * 128;
            int row = f >> 3, kc = f & 7;
            const __half* src = g_xh + (size_t)(m0 + row) * K_DIM + kb + kc * 8;
            CP_ASYNC16(sA + (uint32_t)(row * A_PITCH + kc * 8) * 2, src);
        }
        #pragma unroll
        for (int i = 0; i < 8; i++) {                // B: 128 rows x 8 chunks(16B)
            int f   = tid + i * 128;
            int row = f >> 3, kc = f & 7;
            const __half* src = g_Wh + (size_t)(n0 + row) * K_DIM + kb + kc * 8;
            CP_ASYNC16(sB + (uint32_t)(row * A_PITCH + kc * 8) * 2, src);
        }
        CP_COMMIT();
    };

    auto compute = [&](int buf) {
        const __half* As = smem + buf * STG_H;
        const __half* Bs = As + A_SZ;
        const uint32_t* A32 = reinterpret_cast<const uint32_t*>(As);
        const uint32_t* B32 = reinterpret_cast<const uint32_t*>(Bs);
        #pragma unroll
        for (int ks = 0; ks < 4; ks++) {             // 4 x k16 per chunk
            const int kb = ks * 8;                   // half2 units
            uint32_t af[4][4];
            #pragma unroll
            for (int mt = 0; mt < 4; mt++) {
                int r0 = wm * 64 + mt * 16 + g;
                const uint32_t* a0 = A32 + (r0    ) * (A_PITCH / 2) + kb;
                const uint32_t* a1 = A32 + (r0 + 8) * (A_PITCH / 2) + kb;
                af[mt][0] = a0[tg];
                af[mt][1] = a1[tg];
                af[mt][2] = a0[tg + 4];
                af[mt][3] = a1[tg + 4];
            }
            uint32_t bb[8][2];
            #pragma unroll
            for (int nt = 0; nt < 8; nt++) {
                int c0 = wn * 64 + nt * 8 + g;
                const uint32_t* bp = B32 + c0 * (A_PITCH / 2) + kb;
                bb[nt][0] = bp[tg];
                bb[nt][1] = bp[tg + 4];
            }
            #pragma unroll
            for (int mt = 0; mt < 4; mt++)
                #pragma unroll
                for (int nt = 0; nt < 8; nt++)
                    mma16(acc[mt][nt], af[mt], bb[nt]);
        }
    };

    load_stage(0, 0);
    load_stage(1, 1);
    #pragma unroll 1
    for (int kt = 0; kt < NCHUNK; kt++) {
        if (kt + 2 < NCHUNK) {
            load_stage(kt + 2, (kt + 2) % NSTAGE);
            CP_WAIT2();
        } else if (kt + 2 == NCHUNK) {
            CP_WAIT1();
        } else {
            CP_WAIT0();
        }
        __syncthreads();
        compute(kt % NSTAGE);
        __syncthreads();
    }

    // ---------------- epilogue: gate partials (reuse stage smem) ----------------
    float* sWg = reinterpret_cast<float*>(smem);     // 128*NQ floats
    for (int i = tid; i < H_DIM * NQ; i += 128)
        sWg[i] = g_Wg2[(size_t)e * H_DIM * NQ + i];
    __syncthreads();

    float bias[8][2];
    #pragma unroll
    for (int nt = 0; nt < 8; nt++) {
        int col = n0 + wn * 64 + nt * 8 + 2 * tg;
        bias[nt][0] = g_bpack[col];
        bias[nt][1] = g_bpack[col + 1];
    }

    #pragma unroll
    for (int half = 0; half < 2; half++) {
        float part[4][NQ];
        #pragma unroll
        for (int r = 0; r < 4; r++)
            #pragma unroll
            for (int q = 0; q < NQ; q++) part[r][q] = 0.f;

        #pragma unroll
        for (int nt = 0; nt < 8; nt++)
            #pragma unroll
            for (int h2 = 0; h2 < 2; h2++) {
                int hh = wn * 64 + nt * 8 + 2 * tg + h2;
                float w[NQ];
                #pragma unroll
                for (int q = 0; q < NQ; q++) w[q] = sWg[hh * NQ + q];
                #pragma unroll
                for (int mt2 = 0; mt2 < 2; mt2++)
                    #pragma unroll
                    for (int rr = 0; rr < 2; rr++) {
                        float v = acc[half * 2 + mt2][nt][rr * 2 + h2] + bias[nt][h2];
                        #pragma unroll
                        for (int q = 0; q < NQ; q++) part[mt2 * 2 + rr][q] += v * w[q];
                    }
            }

        #pragma unroll
        for (int r = 0; r < 4; r++) {
            #pragma unroll
            for (int q = 0; q < NQ; q++) {
                part[r][q] += __shfl_xor_sync(0xffffffffu, part[r][q], 1);
                part[r][q] += __shfl_xor_sync(0xffffffffu, part[r][q], 2);
            }
            if (tg == 0) {
                int mt = half * 2 + (r >> 1);
                int row = m0 + wm * 64 + mt * 16 + g + (r & 1) * 8;
                float* dst = g_part + (((size_t)(e * 2 + wn) * B_TOK + row) << 4);
                reinterpret_cast<float4*>(dst)[0] =
                    make_float4(part[r][0], part[r][1], part[r][2],  part[r][3]);
                reinterpret_cast<float4*>(dst)[1] =
                    make_float4(part[r][4], part[r][5], part[r][6],  part[r][7]);
                reinterpret_cast<float4*>(dst)[2] =
                    make_float4(part[r][8], part[r][9], part[r][10], part[r][11]);
                reinterpret_cast<float4*>(dst)[3] =
                    make_float4(part[r][12], part[r][13], 0.f, 0.f);
            }
        }
    }
}

// ---------------- kernel 3: combine partials, softmax, output -------------------
__global__ __launch_bounds__(256) void gate_kernel(const float* __restrict__ bg,
                                                   const float* __restrict__ bt,
                                                   float* __restrict__ out) {
    const int b = blockIdx.x * 256 + threadIdx.x;

    float lg[12];
    #pragma unroll
    for (int q = 0; q < 12; q++) lg[q] = 0.f;
    float dots[NE][2];
    #pragma unroll
    for (int e = 0; e < NE; e++) { dots[e][0] = 0.f; dots[e][1] = 0.f; }

    #pragma unroll
    for (int s = 0; s < 16; s++) {
        const float4* p =
            reinterpret_cast<const float4*>(g_part + (((size_t)s * B_TOK + b) << 4));
        float4 v0 = p[0], v1 = p[1], v2 = p[2], v3 = p[3];
        lg[0] += v0.x; lg[1] += v0.y; lg[2]  += v0.z; lg[3]  += v0.w;
        lg[4] += v1.x; lg[5] += v1.y; lg[6]  += v1.z; lg[7]  += v1.w;
        lg[8] += v2.x; lg[9] += v2.y; lg[10] += v2.z; lg[11] += v2.w;
        int e = s >> 1;
        dots[e][0] += v3.x; dots[e][1] += v3.y;
    }

    #pragma unroll
    for (int t = 0; t < T_NUM; t++) {
        float l[ETOT];
        #pragma unroll
        for (int j = 0; j < ETOT; j++) l[j] = lg[t * ETOT + j] + bg[t * ETOT + j];
        float m = l[0];
        #pragma unroll
        for (int j = 1; j < ETOT; j++) m = fmaxf(m, l[j]);
        float ex[ETOT], ssum = 0.f;
        #pragma unroll
        for (int j = 0; j < ETOT; j++) { ex[j] = expf(l[j] - m); ssum += ex[j]; }
        float inv = 1.f / ssum;
        float o = 0.f;
        #pragma unroll
        for (int eo = 0; eo < ETOT; eo++) {
            int e2 = (eo < 2) ? (2 * t + eo) : (eo + 2);
            o += ex[eo] * inv * dots[e2][t];
        }
        out[t * B_TOK + b] = o + bt[t];
    }
}

// ---------------- launch ----------------
extern "C" void kernel_launch(void* const* d_in, const int* in_sizes, int n_in,
                              void* d_out, int out_size) {
    const float* x  = (const float*)d_in[0];
    const float* Wc = (const float*)d_in[1];
    const float* bc = (const float*)d_in[2];
    const float* Ws = (const float*)d_in[3];
    const float* bs = (const float*)d_in[4];
    const float* Wg = (const float*)d_in[5];
    const float* bg = (const float*)d_in[6];
    const float* Wt = (const float*)d_in[7];
    const float* bt = (const float*)d_in[8];
    float* out = (float*)d_out;

    prep_kernel<<<(B_TOK * K_DIM / 4) / 256, 256>>>(x, Wc, bc, Ws, bs, Wg, Wt);

    cudaFuncSetAttribute(gemm_kernel, cudaFuncAttributeMaxDynamicSharedMemorySize,
                         SMEM_BYTES);
    gemm_kernel<<<dim3(NE, B_TOK / BM), 128, SMEM_BYTES>>>();

    gate_kernel<<<B_TOK / 256, 256>>>(bg, bt, out);
}